// round 5
// baseline (speedup 1.0000x reference)
#include <cuda_runtime.h>
#include <cuda_bf16.h>
#include <cstdint>

#define N_NODES 100000
#define N_EDGES 1000000
#define D 64
#define LATENT 32
#define OUT_DIM 64
#define EPB 128                    // edges per block
#define NB_EDGE 7813               // ceil(1e6 / 128)
#define NB_NODE 1563               // node-projection blocks (64 nodes each)
#define XS2_STRIDE 66
#define SA_STRIDE 36               // word stride (conflict-free fragment LDS)

// Scratch (BSS-zeroed at load; mlp re-zeros its consumed tiles each call)
__device__ float g_hsum[(size_t)N_NODES * LATENT];  // 12.8 MB: Σ proj(edge)
__device__ float g_cnt[N_NODES];
__device__ float g_hpre[(size_t)N_NODES * LATENT];  // node_attr @ W1[0:64]
__device__ float g_G[64 * LATENT];                  // global @ W1[128:192] + b1

// ---------------------------------------------------------------------------
// helpers
// ---------------------------------------------------------------------------
__device__ __forceinline__ uint64_t pack2(float a, float b) {
    uint64_t r; asm("mov.b64 %0, {%1, %2};" : "=l"(r) : "f"(a), "f"(b)); return r;
}
__device__ __forceinline__ void unpack2(uint64_t v, float& a, float& b) {
    asm("mov.b64 {%0, %1}, %2;" : "=f"(a), "=f"(b) : "l"(v));
}
__device__ __forceinline__ void ffma2(uint64_t& acc, uint64_t x, uint64_t w) {
    asm("fma.rn.f32x2 %0, %1, %2, %0;" : "+l"(acc) : "l"(x), "l"(w));
}
// bf16x2 pack: lo half = first (smaller-k) element
__device__ __forceinline__ uint32_t pack_bf16x2(float lo, float hi) {
    uint32_t r; asm("cvt.rn.bf16x2.f32 %0, %1, %2;" : "=r"(r) : "f"(hi), "f"(lo));
    return r;
}
__device__ __forceinline__ float bf16lo_f(uint32_t v) { return __uint_as_float(v << 16); }
__device__ __forceinline__ float bf16hi_f(uint32_t v) { return __uint_as_float(v & 0xFFFF0000u); }

__device__ __forceinline__ void mma_bf16(float d[4],
        uint32_t a0, uint32_t a1, uint32_t a2, uint32_t a3,
        uint32_t b0, uint32_t b1) {
    asm("mma.sync.aligned.m16n8k16.row.col.f32.bf16.bf16.f32 "
        "{%0,%1,%2,%3}, {%4,%5,%6,%7}, {%8,%9}, {%0,%1,%2,%3};"
        : "+f"(d[0]), "+f"(d[1]), "+f"(d[2]), "+f"(d[3])
        : "r"(a0), "r"(a1), "r"(a2), "r"(a3), "r"(b0), "r"(b1));
}
__device__ __forceinline__ void red_add_v4(float* dst, float4 v) {
    asm volatile("red.global.add.v4.f32 [%0], {%1, %2, %3, %4};"
                 :: "l"(dst), "f"(v.x), "f"(v.y), "f"(v.z), "f"(v.w) : "memory");
}

// ---------------------------------------------------------------------------
// Kernel A: [edge-proj-scatter | node-proj | G]
// ---------------------------------------------------------------------------
__global__ __launch_bounds__(256)
void scatter_kernel(const float* __restrict__ edge_attr,
                    const int* __restrict__ recv,
                    const float* __restrict__ node_attr,
                    const float* __restrict__ global_attr,
                    const float* __restrict__ W1,
                    const float* __restrict__ b1) {
    __shared__ __align__(16) uint32_t smem_u[11520];   // 46.08 KB union
    const int tid = threadIdx.x;

    if (blockIdx.x < NB_EDGE) {
        uint32_t* sA_hi = smem_u;            // 128 x 36
        uint32_t* sA_lo = smem_u + 4608;     // 128 x 36
        uint32_t* sB_hi = smem_u + 9216;     // 32 x 36
        uint32_t* sB_lo = smem_u + 10368;    // 32 x 36
        const long long ebase = (long long)blockIdx.x * EPB;

        // stage W1[64:128] as bf16 hi/lo k-pair fragments: sB[n][k2]
        for (int idx = tid; idx < LATENT * 32; idx += 256) {
            int n = idx >> 5, k2 = idx & 31;
            float w0 = W1[(D + 2 * k2) * LATENT + n];
            float w1 = W1[(D + 2 * k2 + 1) * LATENT + n];
            uint32_t hi = pack_bf16x2(w0, w1);
            uint32_t lo = pack_bf16x2(w0 - bf16lo_f(hi), w1 - bf16hi_f(hi));
            sB_hi[n * SA_STRIDE + k2] = hi;
            sB_lo[n * SA_STRIDE + k2] = lo;
        }
        // stage edges as bf16 hi/lo k-pairs: sA[e][k2]
        for (int idx = tid; idx < EPB * 16; idx += 256) {
            int e = idx >> 4, q = idx & 15;
            long long eg = ebase + e;
            float4 v = make_float4(0.f, 0.f, 0.f, 0.f);
            if (eg < N_EDGES)
                v = reinterpret_cast<const float4*>(edge_attr)[eg * 16 + q];
            uint32_t h0 = pack_bf16x2(v.x, v.y);
            uint32_t h1 = pack_bf16x2(v.z, v.w);
            uint32_t l0 = pack_bf16x2(v.x - bf16lo_f(h0), v.y - bf16hi_f(h0));
            uint32_t l1 = pack_bf16x2(v.z - bf16lo_f(h1), v.w - bf16hi_f(h1));
            int r = e * SA_STRIDE + 2 * q;
            sA_hi[r] = h0; sA_hi[r + 1] = h1;
            sA_lo[r] = l0; sA_lo[r + 1] = l1;
        }
        __syncthreads();

        const int lane = tid & 31, w = tid >> 5;
        const int g = lane >> 2, t = lane & 3;
        float d[4][4] = {};
        const int ar0 = (w * 16 + g) * SA_STRIDE;
        const int ar1 = (w * 16 + g + 8) * SA_STRIDE;
        #pragma unroll
        for (int kk = 0; kk < 4; kk++) {
            int o0 = kk * 8 + t, o1 = o0 + 4;
            uint32_t ah0 = sA_hi[ar0 + o0], ah1 = sA_hi[ar1 + o0];
            uint32_t ah2 = sA_hi[ar0 + o1], ah3 = sA_hi[ar1 + o1];
            uint32_t al0 = sA_lo[ar0 + o0], al1 = sA_lo[ar1 + o0];
            uint32_t al2 = sA_lo[ar0 + o1], al3 = sA_lo[ar1 + o1];
            #pragma unroll
            for (int n = 0; n < 4; n++) {
                int nb = (8 * n + g) * SA_STRIDE;
                uint32_t bh0 = sB_hi[nb + o0], bh1 = sB_hi[nb + o1];
                uint32_t bl0 = sB_lo[nb + o0], bl1 = sB_lo[nb + o1];
                mma_bf16(d[n], ah0, ah1, ah2, ah3, bh0, bh1);
                mma_bf16(d[n], al0, al1, al2, al3, bh0, bh1);
                mma_bf16(d[n], ah0, ah1, ah2, ah3, bl0, bl1);
            }
        }
        // permute D through own sA rows -> contiguous float4 per edge
        __syncwarp();
        float* sD = reinterpret_cast<float*>(sA_hi);   // rows stride 36 floats
        #pragma unroll
        for (int n = 0; n < 4; n++) {
            int col = 8 * n + 2 * t;
            *reinterpret_cast<float2*>(&sD[(w * 16 + g) * SA_STRIDE + col]) =
                make_float2(d[n][0], d[n][1]);
            *reinterpret_cast<float2*>(&sD[(w * 16 + g + 8) * SA_STRIDE + col]) =
                make_float2(d[n][2], d[n][3]);
        }
        __syncwarp();
        // scatter: 2 lanes per edge, 4 REDG.128 each
        int e = lane >> 1;
        long long eg = ebase + w * 16 + e;
        if (eg < N_EDGES) {
            int r = __ldg(&recv[eg]);
            float* dst = g_hsum + (size_t)r * LATENT;
            #pragma unroll
            for (int i = 0; i < 4; i++) {
                int c4 = (lane & 1) * 4 + i;
                float4 v = *reinterpret_cast<float4*>(
                    &sD[(w * 16 + e) * SA_STRIDE + 4 * c4]);
                red_add_v4(dst + 4 * c4, v);
            }
            if ((lane & 1) == 0) atomicAdd(&g_cnt[r], 1.0f);
        }
        return;
    }

    if (blockIdx.x < NB_EDGE + NB_NODE) {
        // ---- node projection: hpre[n][j] = node_attr[n][0:64] . W1[0:64][j]
        float2* sW  = reinterpret_cast<float2*>(smem_u);           // 8 KB
        float2* xs2 = reinterpret_cast<float2*>(smem_u + 2048);    // 16.9 KB
        const int tile = (blockIdx.x - NB_EDGE) * 64;

        for (int idx = tid; idx < 1024; idx += 256) {
            int k2 = idx >> 5, j = idx & 31;
            sW[idx] = make_float2(W1[(2 * k2) * LATENT + j],
                                  (float)W1[(2 * k2 + 1) * LATENT + j]);
        }
        const int kq = tid & 15, srow = tid >> 4;
        #pragma unroll
        for (int it = 0; it < 4; it++) {
            int nn = it * 16 + srow, n = tile + nn;
            float4 v = make_float4(0.f, 0.f, 0.f, 0.f);
            if (n < N_NODES)
                v = reinterpret_cast<const float4*>(node_attr)[(size_t)n * 16 + kq];
            xs2[(2 * kq + 0) * XS2_STRIDE + nn] = make_float2(v.x, v.y);
            xs2[(2 * kq + 1) * XS2_STRIDE + nn] = make_float2(v.z, v.w);
        }
        __syncthreads();

        const int lane = tid & 31, p = tid >> 5;
        uint64_t a2[8];
        #pragma unroll
        for (int i = 0; i < 8; i++) a2[i] = pack2(0.f, 0.f);
        #pragma unroll 4
        for (int k2 = 0; k2 < 32; k2++) {
            uint64_t w2 = *reinterpret_cast<const uint64_t*>(&sW[k2 * 32 + lane]);
            const uint64_t* xr =
                reinterpret_cast<const uint64_t*>(&xs2[k2 * XS2_STRIDE + p * 8]);
            #pragma unroll
            for (int i = 0; i < 8; i++) ffma2(a2[i], xr[i], w2);
        }
        #pragma unroll
        for (int i = 0; i < 8; i++) {
            float lo, hi; unpack2(a2[i], lo, hi);
            int n = tile + p * 8 + i;
            if (n < N_NODES) g_hpre[(size_t)n * LATENT + lane] = lo + hi;
        }
        return;
    }

    // ---- G[b][j] = b1[j] + global[b] . W1[128:192][j]
    {
        float* sg = reinterpret_cast<float*>(smem_u);            // 16 KB
        float* sw = reinterpret_cast<float*>(smem_u + 4096);     // 8 KB
        float* sb = reinterpret_cast<float*>(smem_u + 6144);
        for (int i = tid; i < (64 * D) / 4; i += 256)
            reinterpret_cast<float4*>(sg)[i] =
                reinterpret_cast<const float4*>(global_attr)[i];
        for (int i = tid; i < (D * LATENT) / 4; i += 256)
            reinterpret_cast<float4*>(sw)[i] =
                reinterpret_cast<const float4*>(W1 + 2 * D * LATENT)[i];
        if (tid < LATENT) sb[tid] = b1[tid];
        __syncthreads();

        const int j = tid & 31, r0 = (tid >> 5) * 8;
        float acc[8];
        #pragma unroll
        for (int i = 0; i < 8; i++) acc[i] = sb[j];
        #pragma unroll 8
        for (int k = 0; k < D; k++) {
            float w = sw[k * LATENT + j];
            #pragma unroll
            for (int i = 0; i < 8; i++)
                acc[i] = fmaf(sg[(r0 + i) * D + k], w, acc[i]);
        }
        #pragma unroll
        for (int i = 0; i < 8; i++) g_G[(r0 + i) * LATENT + j] = acc[i];
    }
}

// ---------------------------------------------------------------------------
// Kernel B: mean + add + relu + layer2. Block = 64 nodes, warp = 8 nodes.
// ---------------------------------------------------------------------------
__global__ __launch_bounds__(256)
void mlp_kernel(const float* __restrict__ W2,
                const float* __restrict__ b2,
                const int* __restrict__ ng,
                float* __restrict__ out) {
    __shared__ float sW2[LATENT * OUT_DIM];   // 8 KB
    __shared__ float sb2[OUT_DIM];
    __shared__ __align__(16) float hs2[LATENT * XS2_STRIDE];  // j-major h

    const int tid = threadIdx.x;
    const int tile = blockIdx.x * 64;
    const int lane = tid & 31, p = tid >> 5;
    const int nbase = tile + p * 8;

    for (int i = tid; i < LATENT * OUT_DIM; i += 256) sW2[i] = W2[i];
    if (tid < OUT_DIM) sb2[tid] = b2[tid];

    // h = relu(hpre + G + hsum/cnt)
    float h[8];
    #pragma unroll
    for (int i = 0; i < 8; i++) {
        int n = nbase + i;
        float v = 0.f;
        if (n < N_NODES) {
            float inv = 1.0f / fmaxf(g_cnt[n], 1.0f);
            int g = __ldg(&ng[n]);
            v = g_hpre[(size_t)n * LATENT + lane] + g_G[g * LATENT + lane]
              + g_hsum[(size_t)n * LATENT + lane] * inv;
        }
        h[i] = fmaxf(v, 0.f);
    }
    #pragma unroll
    for (int q = 0; q < 4; q++)
        *reinterpret_cast<float2*>(&hs2[lane * XS2_STRIDE + p * 8 + 2 * q]) =
            make_float2(h[2 * q], h[2 * q + 1]);
    __syncthreads();

    // re-zero this tile's scratch (all reads done)
    {
        float4 z = make_float4(0.f, 0.f, 0.f, 0.f);
        #pragma unroll
        for (int s = 0; s < 2; s++) {
            int item = tid + 256 * s;            // 0..511
            int n = tile + (item >> 3);
            if (n < N_NODES)
                reinterpret_cast<float4*>(g_hsum)[(size_t)n * 8 + (item & 7)] = z;
        }
        if (tid < 64 && tile + tid < N_NODES) g_cnt[tile + tid] = 0.f;
    }

    // layer 2
    uint64_t o2[4][2];
    #pragma unroll
    for (int q = 0; q < 4; q++) {
        o2[q][0] = pack2(sb2[lane], sb2[lane]);
        o2[q][1] = pack2(sb2[lane + 32], sb2[lane + 32]);
    }
    #pragma unroll 4
    for (int j = 0; j < LATENT; j++) {
        float wa = sW2[j * OUT_DIM + lane];
        float wb = sW2[j * OUT_DIM + lane + 32];
        uint64_t w0 = pack2(wa, wa);
        uint64_t w1 = pack2(wb, wb);
        const uint64_t* hr =
            reinterpret_cast<const uint64_t*>(&hs2[j * XS2_STRIDE + p * 8]);
        #pragma unroll
        for (int q = 0; q < 4; q++) {
            uint64_t x = hr[q];
            ffma2(o2[q][0], x, w0);
            ffma2(o2[q][1], x, w1);
        }
    }

    #pragma unroll
    for (int q = 0; q < 4; q++) {
        int n0 = nbase + 2 * q;
        float a0, c0, a1, c1;
        unpack2(o2[q][0], a0, c0);
        unpack2(o2[q][1], a1, c1);
        if (n0 < N_NODES) {
            out[(size_t)n0 * OUT_DIM + lane]      = a0;
            out[(size_t)n0 * OUT_DIM + lane + 32] = a1;
        }
        if (n0 + 1 < N_NODES) {
            out[(size_t)(n0 + 1) * OUT_DIM + lane]      = c0;
            out[(size_t)(n0 + 1) * OUT_DIM + lane + 32] = c1;
        }
    }
}

// ---------------------------------------------------------------------------
extern "C" void kernel_launch(void* const* d_in, const int* in_sizes, int n_in,
                              void* d_out, int out_size) {
    const float* node_attr   = (const float*)d_in[0];
    const float* edge_attr   = (const float*)d_in[1];
    const float* global_attr = (const float*)d_in[2];
    const float* W1          = (const float*)d_in[3];
    const float* b1          = (const float*)d_in[4];
    const float* W2          = (const float*)d_in[5];
    const float* b2          = (const float*)d_in[6];
    const int*   recv        = (const int*)d_in[7];
    const int*   ng          = (const int*)d_in[8];
    float* out = (float*)d_out;

    // A) edge projection + scatter (tensor-core bf16-split) + node-proj + G
    scatter_kernel<<<NB_EDGE + NB_NODE + 1, 256>>>(edge_attr, recv, node_attr,
                                                   global_attr, W1, b1);

    // B) mean + relu + layer 2 (+ scratch re-zero)
    mlp_kernel<<<(N_NODES + 63) / 64, 256>>>(W2, b2, ng, out);
}